// round 16
// baseline (speedup 1.0000x reference)
#include <cuda_runtime.h>
#include <cuda_fp16.h>
#include <cstdint>

// Problem constants
#define Bz 4
#define Sz 2048
#define Ez 1024
#define Hz 16
#define Dz 64
#define Mrows (Bz*Sz)          // 8192
#define FF (4*Ez)              // 4096
#define E3 (3*Ez)              // 3072

// ---------------------------------------------------------------------------
// Scratch (allocation-free: __device__ globals)
// ---------------------------------------------------------------------------
__device__ __half g_QKV[(size_t)Mrows*E3];      // fused Q|K|V, row stride 3072
__device__ __half g_ATT[(size_t)Mrows*Ez];
__device__ float  g_X1 [(size_t)Mrows*Ez];      // fp32 residual
__device__ __half g_X1h[(size_t)Mrows*Ez];
__device__ __half g_Hh [(size_t)Mrows*FF];
__device__ __half g_xh [(size_t)Mrows*Ez];
// transposed fp16 weights, layout [N, K]
__device__ __half g_Wqkv[(size_t)E3*Ez];
__device__ __half g_WoT[(size_t)Ez*Ez];
__device__ __half g_W1T[(size_t)FF*Ez];
__device__ __half g_W2T[(size_t)Ez*FF];

// ---------------------------------------------------------------------------
// Helpers
// ---------------------------------------------------------------------------
__device__ __forceinline__ uint32_t smem_u32(const void* p) {
    uint32_t a;
    asm("{ .reg .u64 t; cvta.to.shared.u64 t, %1; cvt.u32.u64 %0, t; }"
        : "=r"(a) : "l"(p));
    return a;
}

__device__ __forceinline__ float ex2f(float x) {
    float r;
    asm("ex2.approx.f32 %0, %1;" : "=f"(r) : "f"(x));
    return r;
}

#define CP_ASYNC16(dst, src) \
    asm volatile("cp.async.cg.shared.global [%0], [%1], 16;" :: "r"(dst), "l"(src))
#define CP_COMMIT() asm volatile("cp.async.commit_group;" ::: "memory")
#define CP_WAIT(n)  asm volatile("cp.async.wait_group %0;" :: "n"(n) : "memory")

#define MMA_F16(d, a0_, a1_, a2_, a3_, b0_, b1_)                            \
    asm volatile(                                                           \
        "mma.sync.aligned.m16n8k16.row.col.f32.f16.f16.f32 "                \
        "{%0,%1,%2,%3}, {%4,%5,%6,%7}, {%8,%9}, {%0,%1,%2,%3};"             \
        : "+f"((d)[0]), "+f"((d)[1]), "+f"((d)[2]), "+f"((d)[3])            \
        : "r"(a0_), "r"(a1_), "r"(a2_), "r"(a3_), "r"(b0_), "r"(b1_))

#define LDSM4(r0, r1, r2, r3, addr)                                         \
    asm volatile("ldmatrix.sync.aligned.m8n8.x4.shared.b16 {%0,%1,%2,%3}, [%4];" \
        : "=r"(r0), "=r"(r1), "=r"(r2), "=r"(r3) : "r"(addr))

#define LDSM4T(r0, r1, r2, r3, addr)                                        \
    asm volatile("ldmatrix.sync.aligned.m8n8.x4.trans.shared.b16 {%0,%1,%2,%3}, [%4];" \
        : "=r"(r0), "=r"(r1), "=r"(r2), "=r"(r3) : "r"(addr))

// ---------------------------------------------------------------------------
// fp32 -> fp16 elementwise convert (for x)
// ---------------------------------------------------------------------------
__global__ void __launch_bounds__(256)
conv_h_kernel(const float4* __restrict__ in, uint2* __restrict__ out, int n4)
{
    const int i = blockIdx.x * 256 + threadIdx.x;
    if (i < n4) {
        const float4 v = in[i];
        __half2 lo = __float22half2_rn(make_float2(v.x, v.y));
        __half2 hi = __float22half2_rn(make_float2(v.z, v.w));
        uint2 u;
        u.x = *(uint32_t*)&lo;
        u.y = *(uint32_t*)&hi;
        out[i] = u;
    }
}

// ---------------------------------------------------------------------------
// Weight transpose + fp16 convert
// ---------------------------------------------------------------------------
__global__ void __launch_bounds__(256)
transpose_h(const float* __restrict__ W, __half* __restrict__ Wt, int K, int N)
{
    __shared__ float tile[32][33];
    const int k0 = blockIdx.x * 32, n0 = blockIdx.y * 32;
    const int tx = threadIdx.x & 31, ty = threadIdx.x >> 5;
    #pragma unroll
    for (int r = 0; r < 32; r += 8)
        tile[ty + r][tx] = W[(size_t)(k0 + ty + r) * N + n0 + tx];
    __syncthreads();
    #pragma unroll
    for (int r = 0; r < 32; r += 8)
        Wt[(size_t)(n0 + ty + r) * K + k0 + tx] = __float2half_rn(tile[tx][ty + r]);
}

__global__ void __launch_bounds__(256)
transpose_h3(const float* __restrict__ Wq, const float* __restrict__ Wk,
             const float* __restrict__ Wv, __half* __restrict__ Wt)
{
    __shared__ float tile[32][33];
    const int K = Ez;
    const float* W = (blockIdx.z == 0) ? Wq : (blockIdx.z == 1) ? Wk : Wv;
    const int k0 = blockIdx.x * 32, n0 = blockIdx.y * 32;
    const int tx = threadIdx.x & 31, ty = threadIdx.x >> 5;
    #pragma unroll
    for (int r = 0; r < 32; r += 8) {
        const int k = k0 + ty + r, n = n0 + tx;
        tile[ty + r][tx] = W[((size_t)(n >> 6) * K + k) * 64 + (n & 63)];
    }
    __syncthreads();
    const size_t nbase = (size_t)blockIdx.z * Ez;
    #pragma unroll
    for (int r = 0; r < 32; r += 8) {
        const int n = n0 + ty + r, k = k0 + tx;
        Wt[(nbase + n) * K + k] = __float2half_rn(tile[tx][ty + r]);
    }
}

// ---------------------------------------------------------------------------
// FP16 tensor-core GEMM: C[M,N] = A[M,K] @ Bt[N,K]^T  (+ epilogues)
// Block tile 128(m) x 128(n), BK=32, 256 threads, 8 warps of 64x32,
// 3-stage cp.async pipeline, 2 CTAs/SM (4 warps per SMSP).
// EPI: 0 none, 1 +bias+ReLU, 2 +bias+residual(fp32)
// OMODE: 0 fp32 out, 1 fp16 out, 2 both
// ---------------------------------------------------------------------------
#define GSA 40                         // smem row stride in halves (32 + 8 pad)
#define A_HALVES (128 * GSA)           // 5120
#define B_HALVES (128 * GSA)           // 5120
#define STG_HALVES (A_HALVES + B_HALVES)
#define GEMM_SMEM_BYTES (3 * STG_HALVES * 2)   // 61440

template<int EPI, int OMODE>
__global__ void __launch_bounds__(256, 2)
hgemm(const __half* __restrict__ A, const __half* __restrict__ Bt,
      const float* __restrict__ bias, const float* __restrict__ res,
      float* __restrict__ Cf, __half* __restrict__ Ct, int N, int K)
{
    extern __shared__ __half smh[];
    const uint32_t sb = smem_u32(smh);

    const int tid  = threadIdx.x;
    const int lane = tid & 31;
    const int g    = lane >> 2;
    const int t    = lane & 3;
    const int warp = tid >> 5;
    const int wm   = (warp & 1) * 64;     // 2 warps in m
    const int wn   = (warp >> 1) * 32;    // 4 warps in n

    const int row0 = blockIdx.y * 128;
    const int col0 = blockIdx.x * 128;

    // ldmatrix lane offsets
    const int a_row = (lane & 7) + ((lane >> 3) & 1) * 8;
    const int a_col = (lane >> 4) * 8;
    const int b_row = (lane & 7) + (lane >> 4) * 8;
    const int b_col = ((lane >> 3) & 1) * 8;

    const int nkt = K / 32;

    auto load_tile = [&](int kt, int stg) {
        const int kk = kt * 32;
        const uint32_t base = sb + (uint32_t)stg * STG_HALVES * 2;
        #pragma unroll
        for (int i = 0; i < 2; i++) {
            const int c = tid + i * 256, row = c >> 2, k8 = (c & 3) * 8;
            CP_ASYNC16(base + (uint32_t)(row * GSA + k8) * 2,
                       A + (size_t)(row0 + row) * K + kk + k8);
        }
        #pragma unroll
        for (int i = 0; i < 2; i++) {
            const int c = tid + i * 256, row = c >> 2, k8 = (c & 3) * 8;
            CP_ASYNC16(base + (uint32_t)(A_HALVES + row * GSA + k8) * 2,
                       Bt + (size_t)(col0 + row) * K + kk + k8);
        }
        CP_COMMIT();
    };

    float acc[4][4][4];
    #pragma unroll
    for (int mt = 0; mt < 4; mt++)
        #pragma unroll
        for (int nt = 0; nt < 4; nt++)
            #pragma unroll
            for (int i = 0; i < 4; i++) acc[mt][nt][i] = 0.f;

    load_tile(0, 0);
    load_tile(1, 1);

    int stg = 0;
    for (int kt = 0; kt < nkt; kt++) {
        CP_WAIT(1);
        __syncthreads();
        if (kt + 2 < nkt) load_tile(kt + 2, (stg + 2) % 3);

        const uint32_t sAb = sb + (uint32_t)stg * STG_HALVES * 2;
        const uint32_t sBb = sAb + (uint32_t)A_HALVES * 2;

        #pragma unroll
        for (int kc = 0; kc < 2; kc++) {
            uint32_t af[4][4];
            #pragma unroll
            for (int mt = 0; mt < 4; mt++) {
                LDSM4(af[mt][0], af[mt][1], af[mt][2], af[mt][3],
                      sAb + (uint32_t)((wm + mt * 16 + a_row) * GSA + kc * 16 + a_col) * 2);
            }
            uint32_t bf[4][2];
            #pragma unroll
            for (int ntp = 0; ntp < 2; ntp++) {
                LDSM4(bf[2 * ntp][0], bf[2 * ntp][1], bf[2 * ntp + 1][0], bf[2 * ntp + 1][1],
                      sBb + (uint32_t)((wn + ntp * 16 + b_row) * GSA + kc * 16 + b_col) * 2);
            }
            #pragma unroll
            for (int mt = 0; mt < 4; mt++)
                #pragma unroll
                for (int nt = 0; nt < 4; nt++)
                    MMA_F16(acc[mt][nt], af[mt][0], af[mt][1], af[mt][2], af[mt][3],
                            bf[nt][0], bf[nt][1]);
        }
        stg = (stg + 1) % 3;
        __syncthreads();
    }

    // ---- epilogue ----
    #pragma unroll
    for (int mt = 0; mt < 4; mt++) {
        #pragma unroll
        for (int nt = 0; nt < 4; nt++) {
            const int r = row0 + wm + mt * 16 + g;
            const int c = col0 + wn + nt * 8 + 2 * t;
            float2 v0 = make_float2(acc[mt][nt][0], acc[mt][nt][1]);
            float2 v1 = make_float2(acc[mt][nt][2], acc[mt][nt][3]);
            if (EPI != 0) {
                const float2 bb = *(const float2*)(bias + c);
                v0.x += bb.x; v0.y += bb.y;
                v1.x += bb.x; v1.y += bb.y;
            }
            if (EPI == 2) {
                const float2 r0v = *(const float2*)(res + (size_t)r * N + c);
                const float2 r1v = *(const float2*)(res + (size_t)(r + 8) * N + c);
                v0.x += r0v.x; v0.y += r0v.y;
                v1.x += r1v.x; v1.y += r1v.y;
            }
            if (EPI == 1) {
                v0.x = fmaxf(v0.x, 0.f); v0.y = fmaxf(v0.y, 0.f);
                v1.x = fmaxf(v1.x, 0.f); v1.y = fmaxf(v1.y, 0.f);
            }
            if (OMODE == 0 || OMODE == 2) {
                *(float2*)(Cf + (size_t)r * N + c) = v0;
                *(float2*)(Cf + (size_t)(r + 8) * N + c) = v1;
            }
            if (OMODE == 1 || OMODE == 2) {
                __half2 h0 = __float22half2_rn(v0);
                __half2 h1 = __float22half2_rn(v1);
                *(__half2*)(Ct + (size_t)r * N + c) = h0;
                *(__half2*)(Ct + (size_t)(r + 8) * N + c) = h1;
            }
        }
    }
}

// ---------------------------------------------------------------------------
// Tensor-core causal flash attention (fp16 mma, fp32 softmax/accum).
// qb REVERSED so heavy (long-diagonal) CTAs launch first -> no straggler tail.
// ---------------------------------------------------------------------------
#define FST 72
#define FT_HALVES (128 * FST)                    // 9216
#define FLASH_SMEM_BYTES (5 * FT_HALVES * 2)     // 92160
#define KL2 0.045084402f                          // (1/32) * log2(e)

__global__ void __launch_bounds__(256, 1)
flash_tc(const __half* __restrict__ QKV, __half* __restrict__ O)
{
    extern __shared__ __half fsm[];
    const uint32_t sb = smem_u32(fsm);

    const int qb = (gridDim.x - 1) - blockIdx.x;   // heavy CTAs first
    const int bh = blockIdx.y;
    const int b  = bh >> 4;
    const int h  = bh & 15;

    const int tid  = threadIdx.x;
    const int lane = tid & 31;
    const int g    = lane >> 2;
    const int t    = lane & 3;
    const int w    = tid >> 5;

    const __half* Qg = QKV + (size_t)h * Dz;
    const __half* Kg = QKV + Ez + (size_t)h * Dz;
    const __half* Vg = QKV + 2 * Ez + (size_t)h * Dz;

    const uint32_t QO = 0;
    const uint32_t KO[2] = { FT_HALVES, 3 * FT_HALVES };
    const uint32_t VO[2] = { 2 * FT_HALVES, 4 * FT_HALVES };

    // ---- stage Q tile ----
    #pragma unroll
    for (int i = 0; i < 4; i++) {
        const int c = tid + i * 256;
        const int row = c >> 3, h8 = (c & 7) * 8;
        const __half* src = Qg + ((size_t)(b * Sz + qb * 128 + row)) * E3 + h8;
        *(uint4*)(fsm + QO + row * FST + h8) = *(const uint4*)src;
    }

    auto load_kv = [&](int kt, int buf) {
        #pragma unroll
        for (int i = 0; i < 4; i++) {
            const int c = tid + i * 256;
            const int row = c >> 3, h8 = (c & 7) * 8;
            const size_t roff = ((size_t)(b * Sz + kt * 128 + row)) * E3 + h8;
            CP_ASYNC16(sb + (KO[buf] + row * FST + h8) * 2, Kg + roff);
            CP_ASYNC16(sb + (VO[buf] + row * FST + h8) * 2, Vg + roff);
        }
        CP_COMMIT();
    };

    load_kv(0, 0);
    __syncthreads();

    // ---- Q fragments ----
    const int a_row = (lane & 7) + ((lane >> 3) & 1) * 8;
    const int a_col = (lane >> 4) * 8;
    uint32_t aq[4][4];
    #pragma unroll
    for (int kc = 0; kc < 4; kc++) {
        LDSM4(aq[kc][0], aq[kc][1], aq[kc][2], aq[kc][3],
              sb + (QO + (w * 16 + a_row) * FST + kc * 16 + a_col) * 2);
    }

    float mA = -1e30f, mB = -1e30f, lA = 0.f, lB = 0.f;
    float o[8][4];
    #pragma unroll
    for (int i = 0; i < 8; i++)
        #pragma unroll
        for (int j = 0; j < 4; j++) o[i][j] = 0.f;

    const int qrA = qb * 128 + w * 16 + g;
    const int qrB = qrA + 8;

    const int b_row  = (lane & 7);
    const int b_colq = (lane >> 3) * 8;
    const int v_row  = (lane >> 3) * 8 + (lane & 7);

    const int ntiles = qb + 1;
    for (int kt = 0; kt < ntiles; kt++) {
        const int buf = kt & 1;
        CP_WAIT(0);
        __syncthreads();
        if (kt + 1 < ntiles) load_kv(kt + 1, buf ^ 1);

        // ---- S = Q K^T ----
        float s[16][4];
        #pragma unroll
        for (int nt = 0; nt < 16; nt++)
            #pragma unroll
            for (int i = 0; i < 4; i++) s[nt][i] = 0.f;

        #pragma unroll
        for (int nt = 0; nt < 16; nt++) {
            #pragma unroll
            for (int kcp = 0; kcp < 2; kcp++) {
                uint32_t b0, b1, b2, b3;
                LDSM4(b0, b1, b2, b3,
                      sb + (KO[buf] + (nt * 8 + b_row) * FST + kcp * 32 + b_colq) * 2);
                MMA_F16(s[nt], aq[2 * kcp][0], aq[2 * kcp][1], aq[2 * kcp][2], aq[2 * kcp][3], b0, b1);
                MMA_F16(s[nt], aq[2 * kcp + 1][0], aq[2 * kcp + 1][1], aq[2 * kcp + 1][2], aq[2 * kcp + 1][3], b2, b3);
            }
        }

        // ---- causal mask ----
        if (kt == qb) {
            #pragma unroll
            for (int nt = 0; nt < 16; nt++) {
                const int key = kt * 128 + nt * 8 + 2 * t;
                if (key     > qrA) s[nt][0] = -1e30f;
                if (key + 1 > qrA) s[nt][1] = -1e30f;
                if (key     > qrB) s[nt][2] = -1e30f;
                if (key + 1 > qrB) s[nt][3] = -1e30f;
            }
        }

        // ---- online softmax ----
        float mxA = -1e30f, mxB = -1e30f;
        #pragma unroll
        for (int nt = 0; nt < 16; nt++) {
            mxA = fmaxf(mxA, fmaxf(s[nt][0], s[nt][1]));
            mxB = fmaxf(mxB, fmaxf(s[nt][2], s[nt][3]));
        }
        mxA = fmaxf(mxA, __shfl_xor_sync(0xffffffffu, mxA, 1));
        mxA = fmaxf(mxA, __shfl_xor_sync(0xffffffffu, mxA, 2));
        mxB = fmaxf(mxB, __shfl_xor_sync(0xffffffffu, mxB, 1));
        mxB = fmaxf(mxB, __shfl_xor_sync(0xffffffffu, mxB, 2));

        const float mAn = fmaxf(mA, mxA);
        const float mBn = fmaxf(mB, mxB);
        const float corrA = ex2f((mA - mAn) * KL2);
        const float corrB = ex2f((mB - mBn) * KL2);
        mA = mAn; mB = mBn;

        float sumA = 0.f, sumB = 0.f;
        uint32_t ph[16][2];
        #pragma unroll
        for (int nt = 0; nt < 16; nt++) {
            const float p0 = ex2f((s[nt][0] - mA) * KL2);
            const float p1 = ex2f((s[nt][1] - mA) * KL2);
            const float p2 = ex2f((s[nt][2] - mB) * KL2);
            const float p3 = ex2f((s[nt][3] - mB) * KL2);
            sumA += p0 + p1; sumB += p2 + p3;
            __half2 hA = __float22half2_rn(make_float2(p0, p1));
            __half2 hB = __float22half2_rn(make_float2(p2, p3));
            ph[nt][0] = *(uint32_t*)&hA;
            ph[nt][1] = *(uint32_t*)&hB;
        }
        sumA += __shfl_xor_sync(0xffffffffu, sumA, 1);
        sumA += __shfl_xor_sync(0xffffffffu, sumA, 2);
        sumB += __shfl_xor_sync(0xffffffffu, sumB, 1);
        sumB += __shfl_xor_sync(0xffffffffu, sumB, 2);
        lA = lA * corrA + sumA;
        lB = lB * corrB + sumB;

        #pragma unroll
        for (int i = 0; i < 8; i++) {
            o[i][0] *= corrA; o[i][1] *= corrA;
            o[i][2] *= corrB; o[i][3] *= corrB;
        }

        // ---- O += P V ----
        #pragma unroll
        for (int ntd = 0; ntd < 8; ntd++) {
            #pragma unroll
            for (int kcp = 0; kcp < 4; kcp++) {
                uint32_t v0, v1, v2, v3;
                LDSM4T(v0, v1, v2, v3,
                       sb + (VO[buf] + (kcp * 32 + v_row) * FST + ntd * 8) * 2);
                MMA_F16(o[ntd], ph[4 * kcp][0],     ph[4 * kcp][1],
                                 ph[4 * kcp + 1][0], ph[4 * kcp + 1][1], v0, v1);
                MMA_F16(o[ntd], ph[4 * kcp + 2][0], ph[4 * kcp + 2][1],
                                 ph[4 * kcp + 3][0], ph[4 * kcp + 3][1], v2, v3);
            }
        }
    }

    // ---- write O (fp16, row stride Ez) ----
    const float invA = 1.f / lA;
    const float invB = 1.f / lB;
    __half* orowA = O + ((size_t)(b * Sz + qrA)) * Ez + h * Dz;
    __half* orowB = O + ((size_t)(b * Sz + qrB)) * Ez + h * Dz;
    #pragma unroll
    for (int ntd = 0; ntd < 8; ntd++) {
        const int c = ntd * 8 + 2 * t;
        __half2 hA = __float22half2_rn(make_float2(o[ntd][0] * invA, o[ntd][1] * invA));
        __half2 hB = __float22half2_rn(make_float2(o[ntd][2] * invB, o[ntd][3] * invB));
        *(__half2*)(orowA + c) = hA;
        *(__half2*)(orowB + c) = hB;
    }
}

// ---------------------------------------------------------------------------
// Launch
// ---------------------------------------------------------------------------
extern "C" void kernel_launch(void* const* d_in, const int* in_sizes, int n_in,
                              void* d_out, int out_size)
{
    const float* x  = (const float*)d_in[0];
    const float* Wq = (const float*)d_in[1];
    const float* Wk = (const float*)d_in[2];
    const float* Wv = (const float*)d_in[3];
    const float* Wo = (const float*)d_in[4];
    const float* bo = (const float*)d_in[5];
    const float* W1 = (const float*)d_in[6];
    const float* b1 = (const float*)d_in[7];
    const float* W2 = (const float*)d_in[8];
    const float* b2 = (const float*)d_in[9];
    float* out = (float*)d_out;

    __half *QKVp, *ATTp, *X1h, *Hh, *xh;
    float  *X1p;
    __half *WqkvT, *WoT, *W1T, *W2T;
    cudaGetSymbolAddress((void**)&QKVp,  g_QKV);
    cudaGetSymbolAddress((void**)&ATTp,  g_ATT);
    cudaGetSymbolAddress((void**)&X1p,   g_X1);
    cudaGetSymbolAddress((void**)&X1h,   g_X1h);
    cudaGetSymbolAddress((void**)&Hh,    g_Hh);
    cudaGetSymbolAddress((void**)&xh,    g_xh);
    cudaGetSymbolAddress((void**)&WqkvT, g_Wqkv);
    cudaGetSymbolAddress((void**)&WoT,   g_WoT);
    cudaGetSymbolAddress((void**)&W1T,   g_W1T);
    cudaGetSymbolAddress((void**)&W2T,   g_W2T);

    cudaFuncSetAttribute(hgemm<0,1>, cudaFuncAttributeMaxDynamicSharedMemorySize, GEMM_SMEM_BYTES);
    cudaFuncSetAttribute(hgemm<2,2>, cudaFuncAttributeMaxDynamicSharedMemorySize, GEMM_SMEM_BYTES);
    cudaFuncSetAttribute(hgemm<1,1>, cudaFuncAttributeMaxDynamicSharedMemorySize, GEMM_SMEM_BYTES);
    cudaFuncSetAttribute(hgemm<2,0>, cudaFuncAttributeMaxDynamicSharedMemorySize, GEMM_SMEM_BYTES);
    cudaFuncSetAttribute(flash_tc,   cudaFuncAttributeMaxDynamicSharedMemorySize, FLASH_SMEM_BYTES);

    const dim3 tblk(256);

    // 0a: x -> fp16
    conv_h_kernel<<<(Mrows * Ez / 4 + 255) / 256, tblk>>>((const float4*)x, (uint2*)xh, Mrows * Ez / 4);

    // 0b: weight transposes (+ fp16 convert), output [N,K]
    transpose_h3<<<dim3(Ez / 32, Ez / 32, 3), tblk>>>(Wq, Wk, Wv, WqkvT);
    transpose_h <<<dim3(Ez / 32, Ez / 32), tblk>>>(Wo, WoT, Ez, Ez);
    transpose_h <<<dim3(Ez / 32, FF / 32), tblk>>>(W1, W1T, Ez, FF);
    transpose_h <<<dim3(FF / 32, Ez / 32), tblk>>>(W2, W2T, FF, Ez);

    const dim3 grid_qkv(E3 / 128, Mrows / 128);  // (24, 64)
    const dim3 grid_e(Ez / 128, Mrows / 128);    // (8, 64)
    const dim3 grid_f(FF / 128, Mrows / 128);    // (32, 64)

    // 1: fused QKV projection (fp16 out, row stride 3072)
    hgemm<0,1><<<grid_qkv, tblk, GEMM_SMEM_BYTES>>>(xh, WqkvT, nullptr, nullptr, nullptr, QKVp, E3, Ez);

    // 2: tensor-core causal flash attention (fp16 out)
    flash_tc<<<dim3(Sz / 128, Bz * Hz), tblk, FLASH_SMEM_BYTES>>>(QKVp, ATTp);

    // 3: x1 = attn @ Wo + bo + x  (fp32 + fp16 out)
    hgemm<2,2><<<grid_e, tblk, GEMM_SMEM_BYTES>>>(ATTp, WoT, bo, x, X1p, X1h, Ez, Ez);

    // 4: h = relu(x1 @ W1 + b1)  (fp16 out)
    hgemm<1,1><<<grid_f, tblk, GEMM_SMEM_BYTES>>>(X1h, W1T, b1, nullptr, nullptr, Hh, FF, Ez);

    // 5: out = x1 + h @ W2 + b2  (fp32 out)
    hgemm<2,0><<<grid_e, tblk, GEMM_SMEM_BYTES>>>(Hh, W2T, b2, X1p, out, nullptr, Ez, FF);
}